// round 4
// baseline (speedup 1.0000x reference)
#include <cuda_runtime.h>
#include <math.h>

// ---------------------------------------------------------------------------
// EmbedMatcher: neighbor GCN encode -> residual MLP + LayerNorm -> 4-step
// LSTM-with-support recurrence -> cosine similarity vs support vector.
//
// Key algebraic optimization: in the recurrence, h_r = [h, support_g] where
// support_g is row-invariant, so  h_r @ w_hh^T = h @ w_hh[:, :256]^T + rvec,
// rvec = w_hh[:, 256:] @ support_g  (computed once). Recurrent GEMM K: 512->256.
// ---------------------------------------------------------------------------

#define NTHREADS 256

// ---------------- scratch (no cudaMalloc allowed) ----------------
constexpr size_t N_BUFQ = 8192UL * 256;   // gather sums, query, row = b*2+side
constexpr size_t N_INVQ = 8192;
constexpr size_t N_BUFS = 16UL * 256;     // gather sums, support (10 rows used)
constexpr size_t N_INVS = 64;
constexpr size_t N_QNB  = 4096UL * 256;   // query_nb
constexpr size_t N_SNB  = 8UL * 256;      // support_nb (5 rows)
constexpr size_t N_HQ   = 4096UL * 512;
constexpr size_t N_HS   = 8UL * 512;
constexpr size_t N_ZQ   = 4096UL * 256;
constexpr size_t N_ZS   = 8UL * 256;
constexpr size_t N_QG   = 4096UL * 256;   // query_g (post-LN)
constexpr size_t N_SLN  = 8UL * 256;
constexpr size_t N_SG   = 256;            // support_g
constexpr size_t N_SN   = 256;            // normalized support_g
constexpr size_t N_XW   = 4096UL * 2048;
constexpr size_t N_ACC  = 4096UL * 2048;
constexpr size_t N_RV   = 2048;
constexpr size_t N_C    = 4096UL * 512;
constexpr size_t N_H    = 4096UL * 256;

constexpr size_t O_BUFQ = 0;
constexpr size_t O_INVQ = O_BUFQ + N_BUFQ;
constexpr size_t O_BUFS = O_INVQ + N_INVQ;
constexpr size_t O_INVS = O_BUFS + N_BUFS;
constexpr size_t O_QNB  = O_INVS + N_INVS;
constexpr size_t O_SNB  = O_QNB  + N_QNB;
constexpr size_t O_HQ   = O_SNB  + N_SNB;
constexpr size_t O_HS   = O_HQ   + N_HQ;
constexpr size_t O_ZQ   = O_HS   + N_HS;
constexpr size_t O_ZS   = O_ZQ   + N_ZQ;
constexpr size_t O_QG   = O_ZS   + N_ZS;
constexpr size_t O_SLN  = O_QG   + N_QG;
constexpr size_t O_SG   = O_SLN  + N_SLN;
constexpr size_t O_SN   = O_SG   + N_SG;
constexpr size_t O_XW   = O_SN   + N_SN;
constexpr size_t O_ACC  = O_XW   + N_XW;
constexpr size_t O_RV   = O_ACC  + N_ACC;
constexpr size_t O_C    = O_RV   + N_RV;
constexpr size_t O_H    = O_C    + N_C;
constexpr size_t SCRATCH_TOTAL = O_H + N_H;

__device__ float g_scratch[SCRATCH_TOTAL];

// ---------------- helpers ----------------
__device__ __forceinline__ float sigf(float x) { return 1.0f / (1.0f + expf(-x)); }

__device__ __forceinline__ float block_sum256(float v, float* sbuf) {
    int t = threadIdx.x;
    sbuf[t] = v;
    __syncthreads();
    #pragma unroll
    for (int s = 128; s > 0; s >>= 1) {
        if (t < s) sbuf[t] += sbuf[t + s];
        __syncthreads();
    }
    float r = sbuf[0];
    __syncthreads();
    return r;
}

// ---------------- gather + sum over 64 neighbors ----------------
// conn: (R, 64, 2) int32. Per row: sum emb[conn[n,0]][0..127] and emb[conn[n,1]].
// Output row = r*rowmul + rowoff; buf row layout [rel_sum(128) | ent_sum(128)].
__global__ void gather_sum_kernel(const int* __restrict__ conn,
                                  const int* __restrict__ deg,
                                  const float* __restrict__ emb,
                                  float* __restrict__ buf,
                                  float* __restrict__ invden,
                                  int rowmul, int rowoff)
{
    __shared__ int sc[128];
    int r = blockIdx.x;
    int t = threadIdx.x;  // 128 threads
    sc[t] = conn[r * 128 + t];
    __syncthreads();
    float s0 = 0.0f, s1 = 0.0f;
    #pragma unroll 4
    for (int n = 0; n < 64; n++) {
        s0 += __ldg(&emb[(size_t)sc[2 * n]     * 128 + t]);
        s1 += __ldg(&emb[(size_t)sc[2 * n + 1] * 128 + t]);
    }
    int row = r * rowmul + rowoff;
    buf[(size_t)row * 256 + t]       = s0;
    buf[(size_t)row * 256 + 128 + t] = s1;
    if (t == 0) invden[row] = 1.0f / (float)max(deg[r], 1);
}

// ---------------- generic "TN" SGEMM: C[m][n] = sum_k A[m][k]*B[n][k] --------
// A: (M,K) row-major lda; B: (N,K) row-major ldb (all weights stored this way).
// Tiles: 128x128x8, 8x8 per thread, 256 threads.
enum { EPI_RAW = 0, EPI_RELU = 1, EPI_RES = 2, EPI_NB = 3 };

template <int EPI>
__global__ __launch_bounds__(256, 2)
void gemm_tn(const float* __restrict__ A, int lda,
             const float* __restrict__ B, int ldb,
             float* __restrict__ C, int ldc,
             int M, int N, int K,
             const float* __restrict__ bias,
             const float* __restrict__ extra)
{
    __shared__ float As[8][132];
    __shared__ float Bs[8][132];
    const int tid  = threadIdx.x;
    const int bm   = blockIdx.y * 128;
    const int bn   = blockIdx.x * 128;
    const int lrow = tid >> 1;          // 0..127
    const int lcol = (tid & 1) << 2;    // 0 or 4
    const int ty   = tid >> 4;          // 0..15
    const int tx   = tid & 15;          // 0..15

    float acc[8][8];
    #pragma unroll
    for (int i = 0; i < 8; i++)
        #pragma unroll
        for (int j = 0; j < 8; j++) acc[i][j] = 0.0f;

    const bool arow_ok = (bm + lrow) < M;
    const float* Aptr = A + (size_t)(bm + lrow) * lda + lcol;
    const float* Bptr = B + (size_t)(bn + lrow) * ldb + lcol;  // N is mult of 128

    for (int k0 = 0; k0 < K; k0 += 8) {
        float4 av = make_float4(0.f, 0.f, 0.f, 0.f);
        if (arow_ok) av = *(const float4*)(Aptr + k0);
        float4 bv = *(const float4*)(Bptr + k0);
        __syncthreads();
        As[lcol + 0][lrow] = av.x; As[lcol + 1][lrow] = av.y;
        As[lcol + 2][lrow] = av.z; As[lcol + 3][lrow] = av.w;
        Bs[lcol + 0][lrow] = bv.x; Bs[lcol + 1][lrow] = bv.y;
        Bs[lcol + 2][lrow] = bv.z; Bs[lcol + 3][lrow] = bv.w;
        __syncthreads();
        #pragma unroll
        for (int kk = 0; kk < 8; kk++) {
            float ar[8], br[8];
            *(float4*)&ar[0] = *(const float4*)&As[kk][ty * 8];
            *(float4*)&ar[4] = *(const float4*)&As[kk][ty * 8 + 4];
            *(float4*)&br[0] = *(const float4*)&Bs[kk][tx * 8];
            *(float4*)&br[4] = *(const float4*)&Bs[kk][tx * 8 + 4];
            #pragma unroll
            for (int i = 0; i < 8; i++)
                #pragma unroll
                for (int j = 0; j < 8; j++)
                    acc[i][j] += ar[i] * br[j];
        }
    }

    #pragma unroll
    for (int i = 0; i < 8; i++) {
        int gm = bm + ty * 8 + i;
        if (gm >= M) continue;
        #pragma unroll
        for (int j = 0; j < 8; j++) {
            int gn = bn + tx * 8 + j;
            float v = acc[i][j];
            if (EPI == EPI_RAW) {
                C[(size_t)gm * ldc + gn] = v;
            } else if (EPI == EPI_RELU) {
                C[(size_t)gm * ldc + gn] = fmaxf(v + bias[gn], 0.0f);
            } else if (EPI == EPI_RES) {
                C[(size_t)gm * ldc + gn] = v + bias[gn] + extra[(size_t)gm * ldc + gn];
            } else {  // EPI_NB: tanh((acc + 64*bias) * invden[m]), remap rows
                float tv = (v + 64.0f * bias[gn]) * extra[gm];
                C[(size_t)(gm >> 1) * 256 + (size_t)(gm & 1) * 128 + gn] = tanhf(tv);
            }
        }
    }
}

// ---------------- layernorm (ddof=1 std), per row of 256 ----------------
__global__ void ln_kernel(const float* __restrict__ Z,
                          const float* __restrict__ g,
                          const float* __restrict__ bb,
                          float* __restrict__ out)
{
    __shared__ float sbuf[256];
    int r = blockIdx.x, t = threadIdx.x;
    float z = Z[(size_t)r * 256 + t];
    float mu = block_sum256(z, sbuf) * (1.0f / 256.0f);
    float d = z - mu;
    float var = block_sum256(d * d, sbuf) * (1.0f / 255.0f);
    out[(size_t)r * 256 + t] = g[t] * d / (sqrtf(var) + 1e-6f) + bb[t];
}

// ---------------- mean over 5 support rows ----------------
__global__ void mean_kernel(const float* __restrict__ Sln, float* __restrict__ sg)
{
    int t = threadIdx.x;
    float s = 0.0f;
    #pragma unroll
    for (int i = 0; i < 5; i++) s += Sln[i * 256 + t];
    sg[t] = s * 0.2f;
}

// ---------------- rvec[n] = sum_k w_hh[n][256+k] * support_g[k] ----------------
__global__ void rvec_kernel(const float* __restrict__ w_hh,
                            const float* __restrict__ sg,
                            float* __restrict__ rv)
{
    int n = blockIdx.x * 256 + threadIdx.x;  // 2048 total
    const float* w = w_hh + (size_t)n * 512 + 256;
    float s = 0.0f;
    #pragma unroll 8
    for (int k = 0; k < 256; k++) s += w[k] * sg[k];
    rv[n] = s;
}

// ---------------- LSTM cell update ----------------
__global__ void cell_kernel(const float* __restrict__ acc,
                            const float* __restrict__ xW,
                            const float* __restrict__ b_ih,
                            const float* __restrict__ b_hh,
                            const float* __restrict__ rvec,
                            float* __restrict__ c,
                            const float* __restrict__ qg,
                            float* __restrict__ h,
                            int step)
{
    int idx = blockIdx.x * 256 + threadIdx.x;  // 4096*512
    int b = idx >> 9;
    int u = idx & 511;
    size_t base = (size_t)b * 2048;
    float gi, gf, gg, go;
    if (step == 0) {  // h_r = 0: gates = xW + b_ih + b_hh
        gi = xW[base + u]        + b_ih[u]        + b_hh[u];
        gf = xW[base + 512 + u]  + b_ih[512 + u]  + b_hh[512 + u];
        gg = xW[base + 1024 + u] + b_ih[1024 + u] + b_hh[1024 + u];
        go = xW[base + 1536 + u] + b_ih[1536 + u] + b_hh[1536 + u];
    } else {
        gi = xW[base + u]        + acc[base + u]        + b_ih[u]        + b_hh[u]        + rvec[u];
        gf = xW[base + 512 + u]  + acc[base + 512 + u]  + b_ih[512 + u]  + b_hh[512 + u]  + rvec[512 + u];
        gg = xW[base + 1024 + u] + acc[base + 1024 + u] + b_ih[1024 + u] + b_hh[1024 + u] + rvec[1024 + u];
        go = xW[base + 1536 + u] + acc[base + 1536 + u] + b_ih[1536 + u] + b_hh[1536 + u] + rvec[1536 + u];
    }
    float cp = (step == 0) ? 0.0f : c[idx];
    float cn = sigf(gf) * cp + sigf(gi) * tanhf(gg);
    c[idx] = cn;
    float hc = sigf(go) * tanhf(cn);
    if (u < 256) h[(size_t)b * 256 + u] = qg[(size_t)b * 256 + u] + hc;
}

// ---------------- normalize support_g ----------------
__global__ void snorm_kernel(const float* __restrict__ sg, float* __restrict__ sn)
{
    __shared__ float sbuf[256];
    int t = threadIdx.x;
    float v = sg[t];
    float n2 = block_sum256(v * v, sbuf);
    sn[t] = v / fmaxf(sqrtf(n2), 1e-12f);
}

// ---------------- final: out[b] = (h[b]/||h[b]||) . sn ----------------
__global__ void final_kernel(const float* __restrict__ h,
                             const float* __restrict__ sn,
                             float* __restrict__ out)
{
    __shared__ float sbuf[256];
    int b = blockIdx.x, t = threadIdx.x;
    float v = h[(size_t)b * 256 + t];
    float dot = block_sum256(v * sn[t], sbuf);
    float n2  = block_sum256(v * v, sbuf);
    if (t == 0) out[b] = dot / fmaxf(sqrtf(n2), 1e-12f);
}

// ---------------- launch ----------------
extern "C" void kernel_launch(void* const* d_in, const int* in_sizes, int n_in,
                              void* d_out, int out_size)
{
    (void)in_sizes; (void)n_in; (void)out_size;
    const int*   q_l_conn = (const int*)  d_in[2];
    const int*   q_l_deg  = (const int*)  d_in[3];
    const int*   q_r_conn = (const int*)  d_in[4];
    const int*   q_r_deg  = (const int*)  d_in[5];
    const int*   s_l_conn = (const int*)  d_in[6];
    const int*   s_l_deg  = (const int*)  d_in[7];
    const int*   s_r_conn = (const int*)  d_in[8];
    const int*   s_r_deg  = (const int*)  d_in[9];
    const float* emb      = (const float*)d_in[10];
    const float* gcn_w    = (const float*)d_in[11];
    const float* gcn_bias = (const float*)d_in[12];
    const float* proj1_w  = (const float*)d_in[13];
    const float* proj1_b  = (const float*)d_in[14];
    const float* proj2_w  = (const float*)d_in[15];
    const float* proj2_b  = (const float*)d_in[16];
    const float* ln_g     = (const float*)d_in[17];
    const float* ln_b     = (const float*)d_in[18];
    const float* w_ih     = (const float*)d_in[19];
    const float* w_hh     = (const float*)d_in[20];
    const float* b_ih     = (const float*)d_in[21];
    const float* b_hh     = (const float*)d_in[22];
    float* out = (float*)d_out;

    float* S = nullptr;
    cudaGetSymbolAddress((void**)&S, g_scratch);
    float* BUFQ = S + O_BUFQ;  float* INVQ = S + O_INVQ;
    float* BUFS = S + O_BUFS;  float* INVS = S + O_INVS;
    float* QNB  = S + O_QNB;   float* SNB  = S + O_SNB;
    float* HQ   = S + O_HQ;    float* HS   = S + O_HS;
    float* ZQ   = S + O_ZQ;    float* ZS   = S + O_ZS;
    float* QG   = S + O_QG;    float* SLN  = S + O_SLN;
    float* SG   = S + O_SG;    float* SN   = S + O_SN;
    float* XW   = S + O_XW;    float* ACC  = S + O_ACC;
    float* RV   = S + O_RV;    float* C    = S + O_C;
    float* H    = S + O_H;

    // 1) gather-sums
    gather_sum_kernel<<<4096, 128>>>(q_l_conn, q_l_deg, emb, BUFQ, INVQ, 2, 0);
    gather_sum_kernel<<<4096, 128>>>(q_r_conn, q_r_deg, emb, BUFQ, INVQ, 2, 1);
    gather_sum_kernel<<<5,    128>>>(s_l_conn, s_l_deg, emb, BUFS, INVS, 2, 0);
    gather_sum_kernel<<<5,    128>>>(s_r_conn, s_r_deg, emb, BUFS, INVS, 2, 1);

    // 2) GCN matvec + tanh -> query_nb / support_nb
    gemm_tn<EPI_NB><<<dim3(1, 64), 256>>>(BUFQ, 256, gcn_w, 256, QNB, 256,
                                          8192, 128, 256, gcn_bias, INVQ);
    gemm_tn<EPI_NB><<<dim3(1, 1), 256>>>(BUFS, 256, gcn_w, 256, SNB, 256,
                                         10, 128, 256, gcn_bias, INVS);

    // 3) support encoder (S=5)
    gemm_tn<EPI_RELU><<<dim3(4, 1), 256>>>(SNB, 256, proj1_w, 256, HS, 512,
                                           5, 512, 256, proj1_b, nullptr);
    gemm_tn<EPI_RES><<<dim3(2, 1), 256>>>(HS, 512, proj2_w, 512, ZS, 256,
                                          5, 256, 512, proj2_b, SNB);
    ln_kernel<<<5, 256>>>(ZS, ln_g, ln_b, SLN);
    mean_kernel<<<1, 256>>>(SLN, SG);

    // 4) query encoder (B=4096)
    gemm_tn<EPI_RELU><<<dim3(4, 32), 256>>>(QNB, 256, proj1_w, 256, HQ, 512,
                                            4096, 512, 256, proj1_b, nullptr);
    gemm_tn<EPI_RES><<<dim3(2, 32), 256>>>(HQ, 512, proj2_w, 512, ZQ, 256,
                                           4096, 256, 512, proj2_b, QNB);
    ln_kernel<<<4096, 256>>>(ZQ, ln_g, ln_b, QG);

    // 5) LSTM recurrence
    gemm_tn<EPI_RAW><<<dim3(16, 32), 256>>>(QG, 256, w_ih, 256, XW, 2048,
                                            4096, 2048, 256, nullptr, nullptr);
    rvec_kernel<<<8, 256>>>(w_hh, SG, RV);
    cell_kernel<<<8192, 256>>>(nullptr, XW, b_ih, b_hh, RV, C, QG, H, 0);
    for (int t = 1; t < 4; t++) {
        gemm_tn<EPI_RAW><<<dim3(16, 32), 256>>>(H, 256, w_hh, 512, ACC, 2048,
                                                4096, 2048, 256, nullptr, nullptr);
        cell_kernel<<<8192, 256>>>(ACC, XW, b_ih, b_hh, RV, C, QG, H, t);
    }

    // 6) cosine similarity
    snorm_kernel<<<1, 256>>>(SG, SN);
    final_kernel<<<4096, 256>>>(H, SN, out);
}

// round 6
// speedup vs baseline: 1.6642x; 1.6642x over previous
#include <cuda_runtime.h>
#include <cuda_bf16.h>
#include <math.h>
#include <stdint.h>

// ---------------------------------------------------------------------------
// EmbedMatcher on GB300 (sm_103, plain PTX target -> mma.sync tensor cores).
//  - Big LSTM GEMMs (XW + 3 recurrent) via mma.sync m16n8k16 bf16 (bf16x3
//    split, fp32 accumulate) -> HMMA on the tensor pipe.
//  - rank-1 factorization: h_r=[h, support_g] -> recurrent K 512->256 + rvec
//  - support encoder fused into one CTA; all gathers merged into one launch.
// ---------------------------------------------------------------------------

__device__ __forceinline__ uint32_t smem_u32(const void* p) {
    uint32_t a;
    asm("{ .reg .u64 t; cvta.to.shared.u64 t, %1; cvt.u32.u64 %0, t; }"
        : "=r"(a) : "l"(p));
    return a;
}

// ================= scratch (no cudaMalloc) =================
constexpr size_t N_BUFQ = 8192UL * 256;
constexpr size_t N_INVQ = 8192;
constexpr size_t N_BUFS = 16UL * 256;
constexpr size_t N_INVS = 64;
constexpr size_t N_QNB  = 4096UL * 256;
constexpr size_t N_HQ   = 4096UL * 512;
constexpr size_t N_ZQ   = 4096UL * 256;
constexpr size_t N_QG   = 4096UL * 256;
constexpr size_t N_SG   = 256;
constexpr size_t N_SN   = 256;
constexpr size_t N_XW   = 4096UL * 2048;
constexpr size_t N_ACC  = 4096UL * 2048;
constexpr size_t N_RV   = 2048;
constexpr size_t N_C    = 4096UL * 512;
constexpr size_t N_H    = 4096UL * 256;

constexpr size_t O_BUFQ = 0;
constexpr size_t O_INVQ = O_BUFQ + N_BUFQ;
constexpr size_t O_BUFS = O_INVQ + N_INVQ;
constexpr size_t O_INVS = O_BUFS + N_BUFS;
constexpr size_t O_QNB  = O_INVS + N_INVS;
constexpr size_t O_HQ   = O_QNB  + N_QNB;
constexpr size_t O_ZQ   = O_HQ   + N_HQ;
constexpr size_t O_QG   = O_ZQ   + N_ZQ;
constexpr size_t O_SG   = O_QG   + N_QG;
constexpr size_t O_SN   = O_SG   + N_SG;
constexpr size_t O_XW   = O_SN   + N_SN;
constexpr size_t O_ACC  = O_XW   + N_XW;
constexpr size_t O_RV   = O_ACC  + N_ACC;
constexpr size_t O_C    = O_RV   + N_RV;
constexpr size_t O_H    = O_C    + N_C;
constexpr size_t SCRATCH_TOTAL = O_H + N_H;
__device__ float g_scratch[SCRATCH_TOTAL];

// bf16 split buffers
constexpr size_t B_QGH = 0;
constexpr size_t B_QGL = B_QGH + 4096UL * 256;
constexpr size_t B_HH  = B_QGL + 4096UL * 256;
constexpr size_t B_HL  = B_HH  + 4096UL * 256;
constexpr size_t B_WIH = B_HL  + 4096UL * 256;
constexpr size_t B_WIL = B_WIH + 2048UL * 256;
constexpr size_t B_WHH = B_WIL + 2048UL * 256;
constexpr size_t B_WHL = B_WHH + 2048UL * 256;
constexpr size_t BF_TOTAL = B_WHL + 2048UL * 256;
__device__ __align__(128) __nv_bfloat16 g_bf[BF_TOTAL];

// ================= helpers =================
__device__ __forceinline__ float sigf(float x) { return 1.0f / (1.0f + expf(-x)); }

__device__ __forceinline__ float block_sum256(float v, float* sbuf) {
    int t = threadIdx.x;
    sbuf[t] = v;
    __syncthreads();
    #pragma unroll
    for (int s = 128; s > 0; s >>= 1) {
        if (t < s) sbuf[t] += sbuf[t + s];
        __syncthreads();
    }
    float r = sbuf[0];
    __syncthreads();
    return r;
}

// ================= fused gather (q_l | q_r | s_l | s_r) =================
__global__ void gather_all_kernel(const int* __restrict__ qlc, const int* __restrict__ qld,
                                  const int* __restrict__ qrc, const int* __restrict__ qrd,
                                  const int* __restrict__ slc, const int* __restrict__ sld,
                                  const int* __restrict__ src_, const int* __restrict__ srd,
                                  const float* __restrict__ emb,
                                  float* __restrict__ bufq, float* __restrict__ invq,
                                  float* __restrict__ bufs, float* __restrict__ invs)
{
    __shared__ int sc[128];
    int b = blockIdx.x;
    const int* conn; const int* deg; float* buf; float* inv; int r, row;
    if (b < 4096)      { r = b;        conn = qlc;  deg = qld; buf = bufq; inv = invq; row = 2 * r; }
    else if (b < 8192) { r = b - 4096; conn = qrc;  deg = qrd; buf = bufq; inv = invq; row = 2 * r + 1; }
    else if (b < 8197) { r = b - 8192; conn = slc;  deg = sld; buf = bufs; inv = invs; row = 2 * r; }
    else               { r = b - 8197; conn = src_; deg = srd; buf = bufs; inv = invs; row = 2 * r + 1; }
    int t = threadIdx.x;  // 128
    sc[t] = conn[r * 128 + t];
    __syncthreads();
    float s0 = 0.0f, s1 = 0.0f;
    #pragma unroll 4
    for (int n = 0; n < 64; n++) {
        s0 += __ldg(&emb[(size_t)sc[2 * n]     * 128 + t]);
        s1 += __ldg(&emb[(size_t)sc[2 * n + 1] * 128 + t]);
    }
    buf[(size_t)row * 256 + t]       = s0;
    buf[(size_t)row * 256 + 128 + t] = s1;
    if (t == 0) inv[row] = 1.0f / (float)max(deg[r], 1);
}

// ================= SIMT TN GEMM (query GCN / proj1 / proj2) =================
enum { EPI_RELU = 1, EPI_RES = 2, EPI_NB = 3 };

template <int EPI>
__global__ __launch_bounds__(256, 2)
void gemm_tn(const float* __restrict__ A, int lda,
             const float* __restrict__ B, int ldb,
             float* __restrict__ C, int ldc,
             int M, int N, int K,
             const float* __restrict__ bias,
             const float* __restrict__ extra)
{
    __shared__ float As[8][132];
    __shared__ float Bs[8][132];
    const int tid  = threadIdx.x;
    const int bm   = blockIdx.y * 128;
    const int bn   = blockIdx.x * 128;
    const int lrow = tid >> 1;
    const int lcol = (tid & 1) << 2;
    const int ty   = tid >> 4;
    const int tx   = tid & 15;

    float acc[8][8];
    #pragma unroll
    for (int i = 0; i < 8; i++)
        #pragma unroll
        for (int j = 0; j < 8; j++) acc[i][j] = 0.0f;

    const bool arow_ok = (bm + lrow) < M;
    const float* Aptr = A + (size_t)(bm + lrow) * lda + lcol;
    const float* Bptr = B + (size_t)(bn + lrow) * ldb + lcol;

    for (int k0 = 0; k0 < K; k0 += 8) {
        float4 av = make_float4(0.f, 0.f, 0.f, 0.f);
        if (arow_ok) av = *(const float4*)(Aptr + k0);
        float4 bv = *(const float4*)(Bptr + k0);
        __syncthreads();
        As[lcol + 0][lrow] = av.x; As[lcol + 1][lrow] = av.y;
        As[lcol + 2][lrow] = av.z; As[lcol + 3][lrow] = av.w;
        Bs[lcol + 0][lrow] = bv.x; Bs[lcol + 1][lrow] = bv.y;
        Bs[lcol + 2][lrow] = bv.z; Bs[lcol + 3][lrow] = bv.w;
        __syncthreads();
        #pragma unroll
        for (int kk = 0; kk < 8; kk++) {
            float ar[8], br[8];
            *(float4*)&ar[0] = *(const float4*)&As[kk][ty * 8];
            *(float4*)&ar[4] = *(const float4*)&As[kk][ty * 8 + 4];
            *(float4*)&br[0] = *(const float4*)&Bs[kk][tx * 8];
            *(float4*)&br[4] = *(const float4*)&Bs[kk][tx * 8 + 4];
            #pragma unroll
            for (int i = 0; i < 8; i++)
                #pragma unroll
                for (int j = 0; j < 8; j++)
                    acc[i][j] += ar[i] * br[j];
        }
    }

    #pragma unroll
    for (int i = 0; i < 8; i++) {
        int gm = bm + ty * 8 + i;
        if (gm >= M) continue;
        #pragma unroll
        for (int j = 0; j < 8; j++) {
            int gn = bn + tx * 8 + j;
            float v = acc[i][j];
            if (EPI == EPI_RELU) {
                C[(size_t)gm * ldc + gn] = fmaxf(v + bias[gn], 0.0f);
            } else if (EPI == EPI_RES) {
                C[(size_t)gm * ldc + gn] = v + bias[gn] + extra[(size_t)gm * ldc + gn];
            } else {  // EPI_NB
                float tv = (v + 64.0f * bias[gn]) * extra[gm];
                C[(size_t)(gm >> 1) * 256 + (size_t)(gm & 1) * 128 + gn] = tanhf(tv);
            }
        }
    }
}

// ================= mma.sync GEMM: C(4096x2048) = A(4096x256) @ B(2048x256)^T
// bf16x3: K' = 768 over segs (Ah,Bh), (Ah,Bl), (Al,Bh); fp32 accumulate.
// CTA 128x128, 8 warps in 2(m)x4(n), warp tile 64x32, k-chunks of 64.
__global__ __launch_bounds__(256, 2)
void mma_gemm(const __nv_bfloat16* __restrict__ Ahi,
              const __nv_bfloat16* __restrict__ Alo,
              const __nv_bfloat16* __restrict__ Bhi,
              const __nv_bfloat16* __restrict__ Blo,
              float* __restrict__ C)
{
    __shared__ __align__(1024) char sa[16384];
    __shared__ __align__(1024) char sb[16384];
    const int tid  = threadIdx.x;
    const int wid  = tid >> 5;
    const int lane = tid & 31;
    const int bm = blockIdx.y * 128;
    const int bn = blockIdx.x * 128;
    const int warp_m = wid & 1;   // 0..1
    const int warp_n = wid >> 1;  // 0..3

    float acc[4][4][4];
    #pragma unroll
    for (int mi = 0; mi < 4; mi++)
        #pragma unroll
        for (int nj = 0; nj < 4; nj++)
            #pragma unroll
            for (int q = 0; q < 4; q++) acc[mi][nj][q] = 0.0f;

    const uint32_t sa_base = smem_u32(sa);
    const uint32_t sb_base = smem_u32(sb);

    // precompute per-lane ldmatrix address offsets (row/chunk patterns)
    // A (x4): row = mbase + (lane&7) + ((lane>>3)&1)*8 ; chunk = ks*2 + (lane>>4)
    const int a_row_off = (lane & 7) + ((lane >> 3) & 1) * 8;
    const int a_ch_off  = lane >> 4;
    // B (x2): row = nbase + (lane&7) ; chunk = ks*2 + ((lane>>3)&1)
    const int b_row_off = lane & 7;
    const int b_ch_off  = (lane >> 3) & 1;

    for (int c = 0; c < 12; c++) {
        const int seg  = c >> 2;
        const int koff = (c & 3) * 64;
        const __nv_bfloat16* Asrc = (seg < 2) ? Ahi : Alo;
        const __nv_bfloat16* Bsrc = (seg == 1) ? Blo : Bhi;
        __syncthreads();
        #pragma unroll
        for (int i = 0; i < 4; i++) {
            int idx = i * 256 + tid;          // 0..1023 16B chunks
            int row = idx >> 3;
            int ch  = idx & 7;
            uint4 va = *(const uint4*)(Asrc + (size_t)(bm + row) * 256 + koff + ch * 8);
            uint4 vb = *(const uint4*)(Bsrc + (size_t)(bn + row) * 256 + koff + ch * 8);
            uint32_t off = (uint32_t)(row * 128 + ch * 16);
            uint32_t sw  = off ^ ((off >> 3) & 0x70);
            *(uint4*)(sa + sw) = va;
            *(uint4*)(sb + sw) = vb;
        }
        __syncthreads();
        #pragma unroll
        for (int ks = 0; ks < 4; ks++) {
            uint32_t a[4][4];
            #pragma unroll
            for (int mi = 0; mi < 4; mi++) {
                uint32_t row = warp_m * 64 + mi * 16 + a_row_off;
                uint32_t ch  = ks * 2 + a_ch_off;
                uint32_t off = row * 128 + ch * 16;
                uint32_t addr = sa_base + (off ^ ((off >> 3) & 0x70));
                asm volatile("ldmatrix.sync.aligned.m8n8.x4.shared.b16 {%0,%1,%2,%3}, [%4];"
                             : "=r"(a[mi][0]), "=r"(a[mi][1]), "=r"(a[mi][2]), "=r"(a[mi][3])
                             : "r"(addr));
            }
            uint32_t b[4][2];
            #pragma unroll
            for (int nj = 0; nj < 4; nj++) {
                uint32_t row = warp_n * 32 + nj * 8 + b_row_off;
                uint32_t ch  = ks * 2 + b_ch_off;
                uint32_t off = row * 128 + ch * 16;
                uint32_t addr = sb_base + (off ^ ((off >> 3) & 0x70));
                asm volatile("ldmatrix.sync.aligned.m8n8.x2.shared.b16 {%0,%1}, [%2];"
                             : "=r"(b[nj][0]), "=r"(b[nj][1])
                             : "r"(addr));
            }
            #pragma unroll
            for (int mi = 0; mi < 4; mi++)
                #pragma unroll
                for (int nj = 0; nj < 4; nj++)
                    asm volatile(
                        "mma.sync.aligned.m16n8k16.row.col.f32.bf16.bf16.f32 "
                        "{%0,%1,%2,%3}, {%4,%5,%6,%7}, {%8,%9}, {%0,%1,%2,%3};"
                        : "+f"(acc[mi][nj][0]), "+f"(acc[mi][nj][1]),
                          "+f"(acc[mi][nj][2]), "+f"(acc[mi][nj][3])
                        : "r"(a[mi][0]), "r"(a[mi][1]), "r"(a[mi][2]), "r"(a[mi][3]),
                          "r"(b[nj][0]), "r"(b[nj][1]));
        }
    }

    // epilogue: d-frag: c0,c1 at (row lane/4, col 2*(lane%4)+{0,1}); c2,c3 at row+8
    #pragma unroll
    for (int mi = 0; mi < 4; mi++) {
        int m0 = bm + warp_m * 64 + mi * 16 + (lane >> 2);
        #pragma unroll
        for (int nj = 0; nj < 4; nj++) {
            int n0 = bn + warp_n * 32 + nj * 8 + (lane & 3) * 2;
            float* p = C + (size_t)m0 * 2048 + n0;
            p[0] = acc[mi][nj][0];
            p[1] = acc[mi][nj][1];
            float* p2 = p + 8 * 2048;
            p2[0] = acc[mi][nj][2];
            p2[1] = acc[mi][nj][3];
        }
    }
}

// ================= fused support encoder (one CTA, 512 threads) =============
__global__ __launch_bounds__(512)
void support_fused(const float* __restrict__ BUFS, const float* __restrict__ INVS,
                   const float* __restrict__ gcn_w, const float* __restrict__ gcn_bias,
                   const float* __restrict__ p1w, const float* __restrict__ p1b,
                   const float* __restrict__ p2w, const float* __restrict__ p2b,
                   const float* __restrict__ ln_g, const float* __restrict__ ln_b,
                   float* __restrict__ SG, float* __restrict__ SN)
{
    __shared__ float sB[10][256];
    __shared__ float sInv[10];
    __shared__ float sNB[5][256];
    __shared__ float sH[5][512];
    __shared__ float sZ[5][256];
    __shared__ float sLN[5][256];
    __shared__ float sg[256];
    const int tid = threadIdx.x;
    const int w = tid >> 5, l = tid & 31;

    for (int i = tid; i < 2560; i += 512) sB[i >> 8][i & 255] = BUFS[i];
    if (tid < 10) sInv[tid] = INVS[tid];
    __syncthreads();

    // GCN: 128 outputs x 10 rows, tanh((dot + 64*bias)*inv), remapped to 5x256
    for (int n = w; n < 128; n += 16) {
        float wreg[8];
        #pragma unroll
        for (int kk = 0; kk < 8; kk++) wreg[kk] = gcn_w[n * 256 + kk * 32 + l];
        for (int r = 0; r < 10; r++) {
            float s = 0.f;
            #pragma unroll
            for (int kk = 0; kk < 8; kk++) s += wreg[kk] * sB[r][kk * 32 + l];
            #pragma unroll
            for (int o = 16; o; o >>= 1) s += __shfl_xor_sync(0xFFFFFFFFu, s, o);
            if (l == 0)
                sNB[r >> 1][(r & 1) * 128 + n] = tanhf((s + 64.f * gcn_bias[n]) * sInv[r]);
        }
    }
    __syncthreads();
    // proj1 + relu
    for (int n = w; n < 512; n += 16) {
        float wreg[8];
        #pragma unroll
        for (int kk = 0; kk < 8; kk++) wreg[kk] = p1w[n * 256 + kk * 32 + l];
        for (int r = 0; r < 5; r++) {
            float s = 0.f;
            #pragma unroll
            for (int kk = 0; kk < 8; kk++) s += wreg[kk] * sNB[r][kk * 32 + l];
            #pragma unroll
            for (int o = 16; o; o >>= 1) s += __shfl_xor_sync(0xFFFFFFFFu, s, o);
            if (l == 0) sH[r][n] = fmaxf(s + p1b[n], 0.f);
        }
    }
    __syncthreads();
    // proj2 + bias + residual
    for (int n = w; n < 256; n += 16) {
        float wreg[16];
        #pragma unroll
        for (int kk = 0; kk < 16; kk++) wreg[kk] = p2w[n * 512 + kk * 32 + l];
        for (int r = 0; r < 5; r++) {
            float s = 0.f;
            #pragma unroll
            for (int kk = 0; kk < 16; kk++) s += wreg[kk] * sH[r][kk * 32 + l];
            #pragma unroll
            for (int o = 16; o; o >>= 1) s += __shfl_xor_sync(0xFFFFFFFFu, s, o);
            if (l == 0) sZ[r][n] = s + p2b[n] + sNB[r][n];
        }
    }
    __syncthreads();
    // layernorm (ddof=1), warp r handles row r
    if (w < 5) {
        float zr[8];
        #pragma unroll
        for (int kk = 0; kk < 8; kk++) zr[kk] = sZ[w][kk * 32 + l];
        float s = 0.f;
        #pragma unroll
        for (int kk = 0; kk < 8; kk++) s += zr[kk];
        #pragma unroll
        for (int o = 16; o; o >>= 1) s += __shfl_xor_sync(0xFFFFFFFFu, s, o);
        float mu = s * (1.f / 256.f);
        float q = 0.f;
        #pragma unroll
        for (int kk = 0; kk < 8; kk++) { float d = zr[kk] - mu; q += d * d; }
        #pragma unroll
        for (int o = 16; o; o >>= 1) q += __shfl_xor_sync(0xFFFFFFFFu, q, o);
        float sig = sqrtf(q * (1.f / 255.f)) + 1e-6f;
        #pragma unroll
        for (int kk = 0; kk < 8; kk++) {
            int ci = kk * 32 + l;
            sLN[w][ci] = ln_g[ci] * (zr[kk] - mu) / sig + ln_b[ci];
        }
    }
    __syncthreads();
    if (tid < 256) {
        float s = 0.f;
        #pragma unroll
        for (int r = 0; r < 5; r++) s += sLN[r][tid];
        float v = s * 0.2f;
        sg[tid] = v;
        SG[tid] = v;
    }
    __syncthreads();
    if (w == 0) {
        float q = 0.f;
        #pragma unroll
        for (int kk = 0; kk < 8; kk++) { float v = sg[kk * 32 + l]; q += v * v; }
        #pragma unroll
        for (int o = 16; o; o >>= 1) q += __shfl_xor_sync(0xFFFFFFFFu, q, o);
        float inv = 1.f / fmaxf(sqrtf(q), 1e-12f);
        #pragma unroll
        for (int kk = 0; kk < 8; kk++) SN[kk * 32 + l] = sg[kk * 32 + l] * inv;
    }
}

// ================= layernorm + bf16 split (query) =================
__global__ void ln_split_kernel(const float* __restrict__ Z,
                                const float* __restrict__ g,
                                const float* __restrict__ bb,
                                float* __restrict__ out,
                                __nv_bfloat16* __restrict__ hi,
                                __nv_bfloat16* __restrict__ lo)
{
    __shared__ float sbuf[256];
    int r = blockIdx.x, t = threadIdx.x;
    float z = Z[(size_t)r * 256 + t];
    float mu = block_sum256(z, sbuf) * (1.0f / 256.0f);
    float d = z - mu;
    float var = block_sum256(d * d, sbuf) * (1.0f / 255.0f);
    float o = g[t] * d / (sqrtf(var) + 1e-6f) + bb[t];
    size_t idx = (size_t)r * 256 + t;
    out[idx] = o;
    __nv_bfloat16 h = __float2bfloat16(o);
    hi[idx] = h;
    lo[idx] = __float2bfloat16(o - __bfloat162float(h));
}

// ================= weight bf16 split (cols [c0, c0+256)) =================
__global__ void split_w_kernel(const float* __restrict__ W, int ldw, int c0,
                               __nv_bfloat16* __restrict__ hi, __nv_bfloat16* __restrict__ lo)
{
    int idx = blockIdx.x * 256 + threadIdx.x;  // rows*256
    int r = idx >> 8, c = idx & 255;
    float v = W[(size_t)r * ldw + c0 + c];
    __nv_bfloat16 h = __float2bfloat16(v);
    hi[idx] = h;
    lo[idx] = __float2bfloat16(v - __bfloat162float(h));
}

// ================= rvec = w_hh[:, 256:] @ support_g =================
__global__ void rvec_kernel(const float* __restrict__ w_hh,
                            const float* __restrict__ sg,
                            float* __restrict__ rv)
{
    int n = blockIdx.x * 256 + threadIdx.x;
    const float* w = w_hh + (size_t)n * 512 + 256;
    float s = 0.0f;
    #pragma unroll 8
    for (int k = 0; k < 256; k++) s += w[k] * sg[k];
    rv[n] = s;
}

// ================= LSTM cell (+ bf16 split of h) =================
__global__ void cell_kernel(const float* __restrict__ acc,
                            const float* __restrict__ xW,
                            const float* __restrict__ b_ih,
                            const float* __restrict__ b_hh,
                            const float* __restrict__ rvec,
                            float* __restrict__ c,
                            const float* __restrict__ qg,
                            float* __restrict__ h,
                            __nv_bfloat16* __restrict__ hh,
                            __nv_bfloat16* __restrict__ hl,
                            int step)
{
    int idx = blockIdx.x * 256 + threadIdx.x;  // 4096*512
    int b = idx >> 9;
    int u = idx & 511;
    size_t base = (size_t)b * 2048;
    float gi, gf, gg, go;
    if (step == 0) {
        gi = xW[base + u]        + b_ih[u]        + b_hh[u];
        gf = xW[base + 512 + u]  + b_ih[512 + u]  + b_hh[512 + u];
        gg = xW[base + 1024 + u] + b_ih[1024 + u] + b_hh[1024 + u];
        go = xW[base + 1536 + u] + b_ih[1536 + u] + b_hh[1536 + u];
    } else {
        gi = xW[base + u]        + acc[base + u]        + b_ih[u]        + b_hh[u]        + rvec[u];
        gf = xW[base + 512 + u]  + acc[base + 512 + u]  + b_ih[512 + u]  + b_hh[512 + u]  + rvec[512 + u];
        gg = xW[base + 1024 + u] + acc[base + 1024 + u] + b_ih[1024 + u] + b_hh[1024 + u] + rvec[1024 + u];
        go = xW[base + 1536 + u] + acc[base + 1536 + u] + b_ih[1536 + u] + b_hh[1536 + u] + rvec[1536 + u];
    }
    float cp = (step == 0) ? 0.0f : c[idx];
    float cn = sigf(gf) * cp + sigf(gi) * tanhf(gg);
    c[idx] = cn;
    float hc = sigf(go) * tanhf(cn);
    if (u < 256) {
        size_t hidx = (size_t)b * 256 + u;
        float hv = qg[hidx] + hc;
        h[hidx] = hv;
        __nv_bfloat16 hi = __float2bfloat16(hv);
        hh[hidx] = hi;
        hl[hidx] = __float2bfloat16(hv - __bfloat162float(hi));
    }
}

// ================= final cosine similarity =================
__global__ void final_kernel(const float* __restrict__ h,
                             const float* __restrict__ sn,
                             float* __restrict__ out)
{
    __shared__ float sbuf[256];
    int b = blockIdx.x, t = threadIdx.x;
    float v = h[(size_t)b * 256 + t];
    float dot = block_sum256(v * sn[t], sbuf);
    float n2  = block_sum256(v * v, sbuf);
    if (t == 0) out[b] = dot / fmaxf(sqrtf(n2), 1e-12f);
}

// ================= launch =================
extern "C" void kernel_launch(void* const* d_in, const int* in_sizes, int n_in,
                              void* d_out, int out_size)
{
    (void)in_sizes; (void)n_in; (void)out_size;
    const int*   q_l_conn = (const int*)  d_in[2];
    const int*   q_l_deg  = (const int*)  d_in[3];
    const int*   q_r_conn = (const int*)  d_in[4];
    const int*   q_r_deg  = (const int*)  d_in[5];
    const int*   s_l_conn = (const int*)  d_in[6];
    const int*   s_l_deg  = (const int*)  d_in[7];
    const int*   s_r_conn = (const int*)  d_in[8];
    const int*   s_r_deg  = (const int*)  d_in[9];
    const float* emb      = (const float*)d_in[10];
    const float* gcn_w    = (const float*)d_in[11];
    const float* gcn_bias = (const float*)d_in[12];
    const float* proj1_w  = (const float*)d_in[13];
    const float* proj1_b  = (const float*)d_in[14];
    const float* proj2_w  = (const float*)d_in[15];
    const float* proj2_b  = (const float*)d_in[16];
    const float* ln_g     = (const float*)d_in[17];
    const float* ln_b     = (const float*)d_in[18];
    const float* w_ih     = (const float*)d_in[19];
    const float* w_hh     = (const float*)d_in[20];
    const float* b_ih     = (const float*)d_in[21];
    const float* b_hh     = (const float*)d_in[22];
    float* out = (float*)d_out;

    float* S = nullptr;
    cudaGetSymbolAddress((void**)&S, g_scratch);
    __nv_bfloat16* BF = nullptr;
    cudaGetSymbolAddress((void**)&BF, g_bf);

    float* BUFQ = S + O_BUFQ;  float* INVQ = S + O_INVQ;
    float* BUFS = S + O_BUFS;  float* INVS = S + O_INVS;
    float* QNB  = S + O_QNB;   float* HQ   = S + O_HQ;
    float* ZQ   = S + O_ZQ;    float* QG   = S + O_QG;
    float* SG   = S + O_SG;    float* SN   = S + O_SN;
    float* XW   = S + O_XW;    float* ACC  = S + O_ACC;
    float* RV   = S + O_RV;    float* C    = S + O_C;
    float* H    = S + O_H;

    __nv_bfloat16* QGH = BF + B_QGH;  __nv_bfloat16* QGL = BF + B_QGL;
    __nv_bfloat16* HH  = BF + B_HH;   __nv_bfloat16* HL  = BF + B_HL;
    __nv_bfloat16* WIH = BF + B_WIH;  __nv_bfloat16* WIL = BF + B_WIL;
    __nv_bfloat16* WHH = BF + B_WHH;  __nv_bfloat16* WHL = BF + B_WHL;

    // 1) all gathers (8202 blocks — stragglers hide inside the big work)
    gather_all_kernel<<<8202, 128>>>(q_l_conn, q_l_deg, q_r_conn, q_r_deg,
                                     s_l_conn, s_l_deg, s_r_conn, s_r_deg,
                                     emb, BUFQ, INVQ, BUFS, INVS);

    // 2) query GCN (SIMT) + fused support encoder
    gemm_tn<EPI_NB><<<dim3(1, 64), 256>>>(BUFQ, 256, gcn_w, 256, QNB, 256,
                                          8192, 128, 256, gcn_bias, INVQ);
    support_fused<<<1, 512>>>(BUFS, INVS, gcn_w, gcn_bias, proj1_w, proj1_b,
                              proj2_w, proj2_b, ln_g, ln_b, SG, SN);

    // 3) query encoder MLP + LN (with bf16 split of QG)
    gemm_tn<EPI_RELU><<<dim3(4, 32), 256>>>(QNB, 256, proj1_w, 256, HQ, 512,
                                            4096, 512, 256, proj1_b, nullptr);
    gemm_tn<EPI_RES><<<dim3(2, 32), 256>>>(HQ, 512, proj2_w, 512, ZQ, 256,
                                           4096, 256, 512, proj2_b, QNB);
    ln_split_kernel<<<4096, 256>>>(ZQ, ln_g, ln_b, QG, QGH, QGL);

    // 4) weight splits + rvec
    split_w_kernel<<<2048, 256>>>(w_ih, 256, 0, WIH, WIL);
    split_w_kernel<<<2048, 256>>>(w_hh, 512, 0, WHH, WHL);
    rvec_kernel<<<8, 256>>>(w_hh, SG, RV);

    // 5) LSTM recurrence — big GEMMs on tensor cores (mma.sync bf16x3)
    mma_gemm<<<dim3(16, 32), 256>>>(QGH, QGL, WIH, WIL, XW);
    cell_kernel<<<8192, 256>>>(nullptr, XW, b_ih, b_hh, RV, C, QG, H, HH, HL, 0);
    for (int t = 1; t < 4; t++) {
        mma_gemm<<<dim3(16, 32), 256>>>(HH, HL, WHH, WHL, ACC);
        cell_kernel<<<8192, 256>>>(ACC, XW, b_ih, b_hh, RV, C, QG, H, HH, HL, t);
    }

    // 6) cosine similarity
    final_kernel<<<4096, 256>>>(H, SN, out);
}

// round 7
// speedup vs baseline: 2.5446x; 1.5291x over previous
#include <cuda_runtime.h>
#include <cuda_bf16.h>
#include <math.h>
#include <stdint.h>

// ---------------------------------------------------------------------------
// EmbedMatcher on GB300 (sm_103 plain PTX target -> mma.sync tensor cores).
//  - ALL large GEMMs via unified mma.sync m16n8k16 bf16x3 kernel (fp32 accum),
//    cp.async double-buffered, templated epilogues.
//  - Dead-gate elimination: only units 0..255 of each LSTM gate are live
//    (h uses h_cell[:, :256]; c[256:] is dead) -> gate GEMM N 2048 -> 1024.
//  - rank-1 factorization: h_r=[h, support_g] -> recurrent K 512->256 + rvec.
//  - support encoder fused into one CTA; all gathers merged into one launch.
// ---------------------------------------------------------------------------

__device__ __forceinline__ uint32_t smem_u32(const void* p) {
    uint32_t a;
    asm("{ .reg .u64 t; cvta.to.shared.u64 t, %1; cvt.u32.u64 %0, t; }"
        : "=r"(a) : "l"(p));
    return a;
}

// ================= fp32 scratch =================
constexpr size_t N_BUFS = 16UL * 256;
constexpr size_t N_INVQ = 8192;
constexpr size_t N_INVS = 64;
constexpr size_t N_QNB  = 4096UL * 256;
constexpr size_t N_ZQ   = 4096UL * 256;
constexpr size_t N_QG   = 4096UL * 256;
constexpr size_t N_SG   = 256;
constexpr size_t N_SN   = 256;
constexpr size_t N_XW   = 4096UL * 1024;
constexpr size_t N_ACC  = 4096UL * 1024;
constexpr size_t N_RV   = 2048;
constexpr size_t N_C    = 4096UL * 256;
constexpr size_t N_H    = 4096UL * 256;

constexpr size_t O_BUFS = 0;
constexpr size_t O_INVQ = O_BUFS + N_BUFS;
constexpr size_t O_INVS = O_INVQ + N_INVQ;
constexpr size_t O_QNB  = O_INVS + N_INVS;
constexpr size_t O_ZQ   = O_QNB  + N_QNB;
constexpr size_t O_QG   = O_ZQ   + N_ZQ;
constexpr size_t O_SG   = O_QG   + N_QG;
constexpr size_t O_SN   = O_SG   + N_SG;
constexpr size_t O_XW   = O_SN   + N_SN;
constexpr size_t O_ACC  = O_XW   + N_XW;
constexpr size_t O_RV   = O_ACC  + N_ACC;
constexpr size_t O_C    = O_RV   + N_RV;
constexpr size_t O_H    = O_C    + N_C;
constexpr size_t SCRATCH_TOTAL = O_H + N_H;
__device__ float g_scratch[SCRATCH_TOTAL];

// ================= bf16 split scratch =================
constexpr size_t B_BUFQH = 0;
constexpr size_t B_BUFQL = B_BUFQH + 8192UL * 256;
constexpr size_t B_QNBH  = B_BUFQL + 8192UL * 256;
constexpr size_t B_QNBL  = B_QNBH  + 4096UL * 256;
constexpr size_t B_HQH   = B_QNBL  + 4096UL * 256;
constexpr size_t B_HQL   = B_HQH   + 4096UL * 512;
constexpr size_t B_QGH   = B_HQL   + 4096UL * 512;
constexpr size_t B_QGL   = B_QGH   + 4096UL * 256;
constexpr size_t B_HH    = B_QGL   + 4096UL * 256;
constexpr size_t B_HL    = B_HH    + 4096UL * 256;
constexpr size_t B_GWH   = B_HL    + 4096UL * 256;
constexpr size_t B_GWL   = B_GWH   + 128UL * 256;
constexpr size_t B_P1H   = B_GWL   + 128UL * 256;
constexpr size_t B_P1L   = B_P1H   + 512UL * 256;
constexpr size_t B_P2H   = B_P1L   + 512UL * 256;
constexpr size_t B_P2L   = B_P2H   + 256UL * 512;
constexpr size_t B_WIHH  = B_P2L   + 256UL * 512;
constexpr size_t B_WIHL  = B_WIHH  + 1024UL * 256;
constexpr size_t B_WHHH  = B_WIHL  + 1024UL * 256;
constexpr size_t B_WHHL  = B_WHHH  + 1024UL * 256;
constexpr size_t BF_TOTAL = B_WHHL + 1024UL * 256;
__device__ __align__(128) __nv_bfloat16 g_bf[BF_TOTAL];

// ================= helpers =================
__device__ __forceinline__ float sigf(float x) { return 1.0f / (1.0f + expf(-x)); }

__device__ __forceinline__ float block_sum256(float v, float* sbuf) {
    int t = threadIdx.x;
    sbuf[t] = v;
    __syncthreads();
    #pragma unroll
    for (int s = 128; s > 0; s >>= 1) {
        if (t < s) sbuf[t] += sbuf[t + s];
        __syncthreads();
    }
    float r = sbuf[0];
    __syncthreads();
    return r;
}

// ================= fused gather -> bf16 splits (query) + fp32 (support) =====
__global__ void gather_all_kernel(const int* __restrict__ qlc, const int* __restrict__ qld,
                                  const int* __restrict__ qrc, const int* __restrict__ qrd,
                                  const int* __restrict__ slc, const int* __restrict__ sld,
                                  const int* __restrict__ src_, const int* __restrict__ srd,
                                  const float* __restrict__ emb,
                                  __nv_bfloat16* __restrict__ bqh, __nv_bfloat16* __restrict__ bql,
                                  float* __restrict__ invq,
                                  float* __restrict__ bufs, float* __restrict__ invs)
{
    __shared__ int sc[128];
    int b = blockIdx.x;
    const int* conn; const int* deg; int r, row; bool isq;
    float* inv;
    if (b < 4096)      { r = b;        conn = qlc;  deg = qld; inv = invq; row = 2 * r;     isq = true;  }
    else if (b < 8192) { r = b - 4096; conn = qrc;  deg = qrd; inv = invq; row = 2 * r + 1; isq = true;  }
    else if (b < 8197) { r = b - 8192; conn = slc;  deg = sld; inv = invs; row = 2 * r;     isq = false; }
    else               { r = b - 8197; conn = src_; deg = srd; inv = invs; row = 2 * r + 1; isq = false; }
    int t = threadIdx.x;  // 128
    sc[t] = conn[r * 128 + t];
    __syncthreads();
    float s0 = 0.0f, s1 = 0.0f;
    #pragma unroll 4
    for (int n = 0; n < 64; n++) {
        s0 += __ldg(&emb[(size_t)sc[2 * n]     * 128 + t]);
        s1 += __ldg(&emb[(size_t)sc[2 * n + 1] * 128 + t]);
    }
    if (isq) {
        size_t i0 = (size_t)row * 256 + t;
        size_t i1 = i0 + 128;
        __nv_bfloat16 h0 = __float2bfloat16(s0);
        __nv_bfloat16 h1 = __float2bfloat16(s1);
        bqh[i0] = h0; bql[i0] = __float2bfloat16(s0 - __bfloat162float(h0));
        bqh[i1] = h1; bql[i1] = __float2bfloat16(s1 - __bfloat162float(h1));
    } else {
        bufs[(size_t)row * 256 + t]       = s0;
        bufs[(size_t)row * 256 + 128 + t] = s1;
    }
    if (t == 0) inv[row] = 1.0f / (float)max(deg[r], 1);
}

// ================= weight splits =================
__global__ void split_lin(const float* __restrict__ W,
                          __nv_bfloat16* __restrict__ hi, __nv_bfloat16* __restrict__ lo)
{
    int idx = blockIdx.x * 256 + threadIdx.x;
    float v = W[idx];
    __nv_bfloat16 h = __float2bfloat16(v);
    hi[idx] = h;
    lo[idx] = __float2bfloat16(v - __bfloat162float(h));
}

// pack live gate rows: out_row in [0,1024), in_row = (out_row>>8)*512 + (out_row&255)
__global__ void split_w_packed(const float* __restrict__ W, int ldw,
                               __nv_bfloat16* __restrict__ hi, __nv_bfloat16* __restrict__ lo)
{
    int idx = blockIdx.x * 256 + threadIdx.x;  // 1024*256
    int orow = idx >> 8, c = idx & 255;
    int irow = (orow >> 8) * 512 + (orow & 255);
    float v = W[(size_t)irow * ldw + c];
    __nv_bfloat16 h = __float2bfloat16(v);
    hi[idx] = h;
    lo[idx] = __float2bfloat16(v - __bfloat162float(h));
}

// ================= unified mma.sync bf16x3 GEMM ==============================
// C(MxN) = A(MxK) @ B(NxK)^T ; A,B given as hi/lo bf16 splits.
// CTA tile 128x128, 8 warps (2m x 4n), warp tile 64x32, K-chunks of 64,
// 2-stage cp.async pipeline. All dims multiples of 128/64 (no predicates).
enum { EPI_RAW = 0, EPI_RELU = 1, EPI_RES = 2, EPI_NB = 3 };

__device__ __forceinline__ void cp16(uint32_t daddr, const void* g) {
    asm volatile("cp.async.cg.shared.global [%0], [%1], 16;" :: "r"(daddr), "l"(g));
}

__device__ __forceinline__ void stage_load(char* sa, char* sb,
                                           const __nv_bfloat16* __restrict__ Asrc,
                                           const __nv_bfloat16* __restrict__ Bsrc,
                                           int lda, int ldb, int bm, int bn,
                                           int koff, int tid)
{
    #pragma unroll
    for (int i = 0; i < 4; i++) {
        int idx = i * 256 + tid;       // 0..1023 16B chunks
        int row = idx >> 3;
        int ch  = idx & 7;
        uint32_t off = (uint32_t)(row * 128 + ch * 16);
        uint32_t sw  = off ^ ((off >> 3) & 0x70);
        cp16(smem_u32(sa + sw), Asrc + (size_t)(bm + row) * lda + koff + ch * 8);
        cp16(smem_u32(sb + sw), Bsrc + (size_t)(bn + row) * ldb + koff + ch * 8);
    }
}

template <int EPI>
__device__ __forceinline__ void epi_store(int gm, int gn, float v,
                                          float* __restrict__ C, int ldc,
                                          const float* __restrict__ bias,
                                          const float* __restrict__ extra,
                                          __nv_bfloat16* __restrict__ outh,
                                          __nv_bfloat16* __restrict__ outl)
{
    if (EPI == EPI_RAW) {
        C[(size_t)gm * ldc + gn] = v;
    } else if (EPI == EPI_RELU) {
        float o = fmaxf(v + bias[gn], 0.0f);
        size_t idx = (size_t)gm * ldc + gn;
        __nv_bfloat16 h = __float2bfloat16(o);
        outh[idx] = h;
        outl[idx] = __float2bfloat16(o - __bfloat162float(h));
    } else if (EPI == EPI_RES) {
        C[(size_t)gm * ldc + gn] = v + bias[gn] + extra[(size_t)gm * ldc + gn];
    } else {  // EPI_NB: tanh((v + 64*bias)*inv[gm]); remap (8192x128)->(4096x256)
        float o = tanhf((v + 64.0f * bias[gn]) * extra[gm]);
        size_t idx = (size_t)(gm >> 1) * 256 + (size_t)(gm & 1) * 128 + gn;
        C[idx] = o;
        __nv_bfloat16 h = __float2bfloat16(o);
        outh[idx] = h;
        outl[idx] = __float2bfloat16(o - __bfloat162float(h));
    }
}

template <int EPI>
__global__ __launch_bounds__(256)
void mma_gemm(const __nv_bfloat16* __restrict__ Ah, const __nv_bfloat16* __restrict__ Al,
              int lda,
              const __nv_bfloat16* __restrict__ Bh, const __nv_bfloat16* __restrict__ Bl,
              int ldb, int K,
              float* __restrict__ C, int ldc,
              const float* __restrict__ bias, const float* __restrict__ extra,
              __nv_bfloat16* __restrict__ outh, __nv_bfloat16* __restrict__ outl)
{
    extern __shared__ char smem[];      // 2 stages x (16KB A + 16KB B)
    const int tid  = threadIdx.x;
    const int wid  = tid >> 5;
    const int lane = tid & 31;
    const int bm = blockIdx.y * 128;
    const int bn = blockIdx.x * 128;
    const int warp_m = wid & 1;
    const int warp_n = wid >> 1;

    float acc[4][4][4];
    #pragma unroll
    for (int mi = 0; mi < 4; mi++)
        #pragma unroll
        for (int nj = 0; nj < 4; nj++)
            #pragma unroll
            for (int q = 0; q < 4; q++) acc[mi][nj][q] = 0.0f;

    const int a_row_off = (lane & 7) + ((lane >> 3) & 1) * 8;
    const int a_ch_off  = lane >> 4;
    const int b_row_off = lane & 7;
    const int b_ch_off  = (lane >> 3) & 1;

    const int nk = K >> 6;       // 64-wide k-chunks per segment
    const int nt = 3 * nk;       // (Ah,Bh) | (Ah,Bl) | (Al,Bh)

    // chunk -> sources + koff
    auto pick = [&](int c, const __nv_bfloat16*& As, const __nv_bfloat16*& Bs, int& koff) {
        int kc = c;
        As = Ah; Bs = Bh;
        if (c >= 2 * nk)      { As = Al; kc = c - 2 * nk; }
        else if (c >= nk)     { Bs = Bl; kc = c - nk; }
        koff = kc * 64;
    };

    {   // prologue: stage 0
        const __nv_bfloat16 *As, *Bs; int koff;
        pick(0, As, Bs, koff);
        stage_load(smem, smem + 16384, As, Bs, lda, ldb, bm, bn, koff, tid);
        asm volatile("cp.async.commit_group;");
    }

    for (int c = 0; c < nt; c++) {
        if (c + 1 < nt) {
            const __nv_bfloat16 *As, *Bs; int koff;
            pick(c + 1, As, Bs, koff);
            char* base = smem + ((c + 1) & 1) * 32768;
            stage_load(base, base + 16384, As, Bs, lda, ldb, bm, bn, koff, tid);
            asm volatile("cp.async.commit_group;");
            asm volatile("cp.async.wait_group 1;");
        } else {
            asm volatile("cp.async.wait_group 0;");
        }
        __syncthreads();

        const uint32_t sa_base = smem_u32(smem + (c & 1) * 32768);
        const uint32_t sb_base = sa_base + 16384;

        #pragma unroll
        for (int ks = 0; ks < 4; ks++) {
            uint32_t a[4][4];
            #pragma unroll
            for (int mi = 0; mi < 4; mi++) {
                uint32_t row = warp_m * 64 + mi * 16 + a_row_off;
                uint32_t ch  = ks * 2 + a_ch_off;
                uint32_t off = row * 128 + ch * 16;
                uint32_t addr = sa_base + (off ^ ((off >> 3) & 0x70));
                asm volatile("ldmatrix.sync.aligned.m8n8.x4.shared.b16 {%0,%1,%2,%3}, [%4];"
                             : "=r"(a[mi][0]), "=r"(a[mi][1]), "=r"(a[mi][2]), "=r"(a[mi][3])
                             : "r"(addr));
            }
            uint32_t b[4][2];
            #pragma unroll
            for (int nj = 0; nj < 4; nj++) {
                uint32_t row = warp_n * 32 + nj * 8 + b_row_off;
                uint32_t ch  = ks * 2 + b_ch_off;
                uint32_t off = row * 128 + ch * 16;
                uint32_t addr = sb_base + (off ^ ((off >> 3) & 0x70));
                asm volatile("ldmatrix.sync.aligned.m8n8.x2.shared.b16 {%0,%1}, [%2];"
                             : "=r"(b[nj][0]), "=r"(b[nj][1])
                             : "r"(addr));
            }
            #pragma unroll
            for (int mi = 0; mi < 4; mi++)
                #pragma unroll
                for (int nj = 0; nj < 4; nj++)
                    asm volatile(
                        "mma.sync.aligned.m16n8k16.row.col.f32.bf16.bf16.f32 "
                        "{%0,%1,%2,%3}, {%4,%5,%6,%7}, {%8,%9}, {%0,%1,%2,%3};"
                        : "+f"(acc[mi][nj][0]), "+f"(acc[mi][nj][1]),
                          "+f"(acc[mi][nj][2]), "+f"(acc[mi][nj][3])
                        : "r"(a[mi][0]), "r"(a[mi][1]), "r"(a[mi][2]), "r"(a[mi][3]),
                          "r"(b[nj][0]), "r"(b[nj][1]));
        }
        __syncthreads();
    }

    // epilogue: d-frag c0,c1 at (lane/4, 2*(lane%4)+{0,1}); c2,c3 at row+8
    #pragma unroll
    for (int mi = 0; mi < 4; mi++) {
        int m0 = bm + warp_m * 64 + mi * 16 + (lane >> 2);
        #pragma unroll
        for (int nj = 0; nj < 4; nj++) {
            int n0 = bn + warp_n * 32 + nj * 8 + (lane & 3) * 2;
            epi_store<EPI>(m0,     n0,     acc[mi][nj][0], C, ldc, bias, extra, outh, outl);
            epi_store<EPI>(m0,     n0 + 1, acc[mi][nj][1], C, ldc, bias, extra, outh, outl);
            epi_store<EPI>(m0 + 8, n0,     acc[mi][nj][2], C, ldc, bias, extra, outh, outl);
            epi_store<EPI>(m0 + 8, n0 + 1, acc[mi][nj][3], C, ldc, bias, extra, outh, outl);
        }
    }
}

// ================= fused support encoder (one CTA, 512 threads) =============
__global__ __launch_bounds__(512)
void support_fused(const float* __restrict__ BUFS, const float* __restrict__ INVS,
                   const float* __restrict__ gcn_w, const float* __restrict__ gcn_bias,
                   const float* __restrict__ p1w, const float* __restrict__ p1b,
                   const float* __restrict__ p2w, const float* __restrict__ p2b,
                   const float* __restrict__ ln_g, const float* __restrict__ ln_b,
                   float* __restrict__ SG, float* __restrict__ SN)
{
    __shared__ float sB[10][256];
    __shared__ float sInv[10];
    __shared__ float sNB[5][256];
    __shared__ float sH[5][512];
    __shared__ float sZ[5][256];
    __shared__ float sLN[5][256];
    __shared__ float sg[256];
    const int tid = threadIdx.x;
    const int w = tid >> 5, l = tid & 31;

    for (int i = tid; i < 2560; i += 512) sB[i >> 8][i & 255] = BUFS[i];
    if (tid < 10) sInv[tid] = INVS[tid];
    __syncthreads();

    for (int n = w; n < 128; n += 16) {
        float wreg[8];
        #pragma unroll
        for (int kk = 0; kk < 8; kk++) wreg[kk] = gcn_w[n * 256 + kk * 32 + l];
        for (int r = 0; r < 10; r++) {
            float s = 0.f;
            #pragma unroll
            for (int kk = 0; kk < 8; kk++) s += wreg[kk] * sB[r][kk * 32 + l];
            #pragma unroll
            for (int o = 16; o; o >>= 1) s += __shfl_xor_sync(0xFFFFFFFFu, s, o);
            if (l == 0)
                sNB[r >> 1][(r & 1) * 128 + n] = tanhf((s + 64.f * gcn_bias[n]) * sInv[r]);
        }
    }
    __syncthreads();
    for (int n = w; n < 512; n += 16) {
        float wreg[8];
        #pragma unroll
        for (int kk = 0; kk < 8; kk++) wreg[kk] = p1w[n * 256 + kk * 32 + l];
        for (int r = 0; r < 5; r++) {
            float s = 0.f;
            #pragma unroll
            for (int kk = 0; kk < 8; kk++) s += wreg[kk] * sNB[r][kk * 32 + l];
            #pragma unroll
            for (int o = 16; o; o >>= 1) s += __shfl_xor_sync(0xFFFFFFFFu, s, o);
            if (l == 0) sH[r][n] = fmaxf(s + p1b[n], 0.f);
        }
    }
    __syncthreads();
    for (int n = w; n < 256; n += 16) {
        float wreg[16];
        #pragma unroll
        for (int kk = 0; kk < 16; kk++) wreg[kk] = p2w[n * 512 + kk * 32 + l];
        for (int r = 0; r < 5; r++) {
            float s = 0.f;
            #pragma unroll
            for (int kk = 0; kk < 16; kk++) s += wreg[kk] * sH[r][kk * 32 + l];
            #pragma unroll
            for (int o = 16; o; o >>= 1) s += __shfl_xor_sync(0xFFFFFFFFu, s, o);
            if (l == 0) sZ[r][n] = s + p2b[n] + sNB[r][n];
        }
    }
    __syncthreads();
    if (w < 5) {
        float zr[8];
        #pragma unroll
        for (int kk = 0; kk < 8; kk++) zr[kk] = sZ[w][kk * 32 + l];
        float s = 0.f;
        #pragma unroll
        for (int kk = 0; kk < 8; kk++) s += zr[kk];
        #pragma unroll
        for (int o = 16; o; o >>= 1) s += __shfl_xor_sync(0xFFFFFFFFu, s, o);
        float mu = s * (1.f / 256.f);
        float q = 0.f;
        #pragma unroll
        for (int kk = 0; kk < 8; kk++) { float d = zr[kk] - mu; q += d * d; }
        #pragma unroll
        for (int o = 16; o; o >>= 1) q += __shfl_xor_sync(0xFFFFFFFFu, q, o);
        float sig = sqrtf(q * (1.f / 255.f)) + 1e-6f;
        #pragma unroll
        for (int kk = 0; kk < 8; kk++) {
            int ci = kk * 32 + l;
            sLN[w][ci] = ln_g[ci] * (zr[kk] - mu) / sig + ln_b[ci];
        }
    }
    __syncthreads();
    if (tid < 256) {
        float s = 0.f;
        #pragma unroll
        for (int r = 0; r < 5; r++) s += sLN[r][tid];
        float v = s * 0.2f;
        sg[tid] = v;
        SG[tid] = v;
    }
    __syncthreads();
    if (w == 0) {
        float q = 0.f;
        #pragma unroll
        for (int kk = 0; kk < 8; kk++) { float v = sg[kk * 32 + l]; q += v * v; }
        #pragma unroll
        for (int o = 16; o; o >>= 1) q += __shfl_xor_sync(0xFFFFFFFFu, q, o);
        float inv = 1.f / fmaxf(sqrtf(q), 1e-12f);
        #pragma unroll
        for (int kk = 0; kk < 8; kk++) SN[kk * 32 + l] = sg[kk * 32 + l] * inv;
    }
}

// ================= layernorm + bf16 split (query) =================
__global__ void ln_split_kernel(const float* __restrict__ Z,
                                const float* __restrict__ g,
                                const float* __restrict__ bb,
                                float* __restrict__ out,
                                __nv_bfloat16* __restrict__ hi,
                                __nv_bfloat16* __restrict__ lo)
{
    __shared__ float sbuf[256];
    int r = blockIdx.x, t = threadIdx.x;
    float z = Z[(size_t)r * 256 + t];
    float mu = block_sum256(z, sbuf) * (1.0f / 256.0f);
    float d = z - mu;
    float var = block_sum256(d * d, sbuf) * (1.0f / 255.0f);
    float o = g[t] * d / (sqrtf(var) + 1e-6f) + bb[t];
    size_t idx = (size_t)r * 256 + t;
    out[idx] = o;
    __nv_bfloat16 h = __float2bfloat16(o);
    hi[idx] = h;
    lo[idx] = __float2bfloat16(o - __bfloat162float(h));
}

// ================= rvec = w_hh @ support_g (cols 256:512) =================
__global__ void rvec_kernel(const float* __restrict__ w_hh,
                            const float* __restrict__ sg,
                            float* __restrict__ rv)
{
    int n = blockIdx.x * 256 + threadIdx.x;  // 0..2047 (original rows)
    const float* w = w_hh + (size_t)n * 512 + 256;
    float s = 0.0f;
    #pragma unroll 8
    for (int k = 0; k < 256; k++) s += w[k] * sg[k];
    rv[n] = s;
}

// ================= LSTM cell, packed gates (4096 x 256 live units) ==========
__global__ void cell_kernel(const float* __restrict__ acc,
                            const float* __restrict__ xW,
                            const float* __restrict__ b_ih,
                            const float* __restrict__ b_hh,
                            const float* __restrict__ rvec,
                            float* __restrict__ c,
                            const float* __restrict__ qg,
                            float* __restrict__ h,
                            __nv_bfloat16* __restrict__ hh,
                            __nv_bfloat16* __restrict__ hl,
                            int step)
{
    int idx = blockIdx.x * 256 + threadIdx.x;  // 4096*256
    int b = idx >> 8;
    int u = idx & 255;
    size_t base = (size_t)b * 1024;
    float gi = xW[base + u]       + b_ih[u]        + b_hh[u];
    float gf = xW[base + 256 + u] + b_ih[512 + u]  + b_hh[512 + u];
    float gg = xW[base + 512 + u] + b_ih[1024 + u] + b_hh[1024 + u];
    float go = xW[base + 768 + u] + b_ih[1536 + u] + b_hh[1536 + u];
    if (step) {
        gi += acc[base + u]       + rvec[u];
        gf += acc[base + 256 + u] + rvec[512 + u];
        gg += acc[base + 512 + u] + rvec[1024 + u];
        go += acc[base + 768 + u] + rvec[1536 + u];
    }
    float cp = step ? c[idx] : 0.0f;
    float cn = sigf(gf) * cp + sigf(gi) * tanhf(gg);
    c[idx] = cn;
    float hv = qg[idx] + sigf(go) * tanhf(cn);
    h[idx] = hv;
    __nv_bfloat16 hi = __float2bfloat16(hv);
    hh[idx] = hi;
    hl[idx] = __float2bfloat16(hv - __bfloat162float(hi));
}

// ================= final cosine similarity =================
__global__ void final_kernel(const float* __restrict__ h,
                             const float* __restrict__ sn,
                             float* __restrict__ out)
{
    __shared__ float sbuf[256];
    int b = blockIdx.x, t = threadIdx.x;
    float v = h[(size_t)b * 256 + t];
    float dot = block_sum256(v * sn[t], sbuf);
    float n2  = block_sum256(v * v, sbuf);
    if (t == 0) out[b] = dot / fmaxf(sqrtf(n2), 1e-12f);
}

// ================= launch =================
extern "C" void kernel_launch(void* const* d_in, const int* in_sizes, int n_in,
                              void* d_out, int out_size)
{
    (void)in_sizes; (void)n_in; (void)out_size;
    const int*   q_l_conn = (const int*)  d_in[2];
    const int*   q_l_deg  = (const int*)  d_in[3];
    const int*   q_r_conn = (const int*)  d_in[4];
    const int*   q_r_deg  = (const int*)  d_in[5];
    const int*   s_l_conn = (const int*)  d_in[6];
    const int*   s_l_deg  = (const int*)  d_in[7];
    const int*   s_r_conn = (const int*)  d_in[8];
    const int*   s_r_deg  = (const int*)  d_in[9];
    const float* emb      = (const float*)d_in[10];
    const float* gcn_w    = (const float*)d_in[11];
    const float* gcn_bias = (const float*)d_in[12];
    const float* proj1_w  = (const float*)d_in[13];
    const float* proj1_b  = (const float*)d_in[14];
    const float* proj2_w  = (const float*)d_in[15];
    const float* proj2_b  = (const float*)d_in[16];
    const float* ln_g     = (const float*)d_in[17];
    const float* ln_b     = (const float*)d_in[18];
    const float* w_ih     = (const float*)d_in[19];
    const float* w_hh     = (const float*)d_in[20];
    const float* b_ih     = (const float*)d_in[21];
    const float* b_hh     = (const float*)d_in[22];
    float* out = (float*)d_out;

    float* S = nullptr;
    cudaGetSymbolAddress((void**)&S, g_scratch);
    __nv_bfloat16* BF = nullptr;
    cudaGetSymbolAddress((void**)&BF, g_bf);

    float* BUFS = S + O_BUFS;  float* INVQ = S + O_INVQ;  float* INVS = S + O_INVS;
    float* QNB  = S + O_QNB;   float* ZQ   = S + O_ZQ;    float* QG   = S + O_QG;
    float* SG   = S + O_SG;    float* SN   = S + O_SN;
    float* XW   = S + O_XW;    float* ACC  = S + O_ACC;   float* RV   = S + O_RV;
    float* C    = S + O_C;     float* H    = S + O_H;

    __nv_bfloat16* BQH = BF + B_BUFQH;  __nv_bfloat16* BQL = BF + B_BUFQL;
    __nv_bfloat16* QNBH = BF + B_QNBH;  __nv_bfloat16* QNBL = BF + B_QNBL;
    __nv_bfloat16* HQH = BF + B_HQH;    __nv_bfloat16* HQL = BF + B_HQL;
    __nv_bfloat16* QGH = BF + B_QGH;    __nv_bfloat16* QGL = BF + B_QGL;
    __nv_bfloat16* HH  = BF + B_HH;     __nv_bfloat16* HL  = BF + B_HL;
    __nv_bfloat16* GWH = BF + B_GWH;    __nv_bfloat16* GWL = BF + B_GWL;
    __nv_bfloat16* P1H = BF + B_P1H;    __nv_bfloat16* P1L = BF + B_P1L;
    __nv_bfloat16* P2H = BF + B_P2H;    __nv_bfloat16* P2L = BF + B_P2L;
    __nv_bfloat16* WIHH = BF + B_WIHH;  __nv_bfloat16* WIHL = BF + B_WIHL;
    __nv_bfloat16* WHHH = BF + B_WHHH;  __nv_bfloat16* WHHL = BF + B_WHHL;

    const int MMA_SMEM = 65536;  // 2 stages x 32KB
    cudaFuncSetAttribute(mma_gemm<EPI_RAW>,  cudaFuncAttributeMaxDynamicSharedMemorySize, MMA_SMEM);
    cudaFuncSetAttribute(mma_gemm<EPI_RELU>, cudaFuncAttributeMaxDynamicSharedMemorySize, MMA_SMEM);
    cudaFuncSetAttribute(mma_gemm<EPI_RES>,  cudaFuncAttributeMaxDynamicSharedMemorySize, MMA_SMEM);
    cudaFuncSetAttribute(mma_gemm<EPI_NB>,   cudaFuncAttributeMaxDynamicSharedMemorySize, MMA_SMEM);

    // 1) gathers (query -> bf16 splits, support -> fp32)
    gather_all_kernel<<<8202, 128>>>(q_l_conn, q_l_deg, q_r_conn, q_r_deg,
                                     s_l_conn, s_l_deg, s_r_conn, s_r_deg,
                                     emb, BQH, BQL, INVQ, BUFS, INVS);

    // 2) weight splits (independent; cheap)
    split_lin<<<128, 256>>>(gcn_w, GWH, GWL);          // 128x256
    split_lin<<<512, 256>>>(proj1_w, P1H, P1L);        // 512x256
    split_lin<<<512, 256>>>(proj2_w, P2H, P2L);        // 256x512
    split_w_packed<<<1024, 256>>>(w_ih, 256, WIHH, WIHL);
    split_w_packed<<<1024, 256>>>(w_hh, 512, WHHH, WHHL);

    // 3) query GCN (tensor) + fused support encoder
    mma_gemm<EPI_NB><<<dim3(1, 64), 256, MMA_SMEM>>>(
        BQH, BQL, 256, GWH, GWL, 256, 256, QNB, 256, gcn_bias, INVQ, QNBH, QNBL);
    support_fused<<<1, 512>>>(BUFS, INVS, gcn_w, gcn_bias, proj1_w, proj1_b,
                              proj2_w, proj2_b, ln_g, ln_b, SG, SN);

    // 4) query MLP on tensor cores
    mma_gemm<EPI_RELU><<<dim3(4, 32), 256, MMA_SMEM>>>(
        QNBH, QNBL, 256, P1H, P1L, 256, 256, nullptr, 512, proj1_b, nullptr, HQH, HQL);
    mma_gemm<EPI_RES><<<dim3(2, 32), 256, MMA_SMEM>>>(
        HQH, HQL, 512, P2H, P2L, 512, 512, ZQ, 256, proj2_b, QNB, nullptr, nullptr);
    ln_split_kernel<<<4096, 256>>>(ZQ, ln_g, ln_b, QG, QGH, QGL);

    // 5) LSTM recurrence (gates packed to 1024 live rows)
    rvec_kernel<<<8, 256>>>(w_hh, SG, RV);
    mma_gemm<EPI_RAW><<<dim3(8, 32), 256, MMA_SMEM>>>(
        QGH, QGL, 256, WIHH, WIHL, 256, 256, XW, 1024, nullptr, nullptr, nullptr, nullptr);
    cell_kernel<<<4096, 256>>>(nullptr, XW, b_ih, b_hh, RV, C, QG, H, HH, HL, 0);
    for (int t = 1; t < 4; t++) {
        mma_gemm<EPI_RAW><<<dim3(8, 32), 256, MMA_SMEM>>>(
            HH, HL, 256, WHHH, WHHL, 256, 256, ACC, 1024, nullptr, nullptr, nullptr, nullptr);
        cell_kernel<<<4096, 256>>>(ACC, XW, b_ih, b_hh, RV, C, QG, H, HH, HL, t);
    }

    // 6) cosine similarity
    final_kernel<<<4096, 256>>>(H, SN, out);
}